// round 1
// baseline (speedup 1.0000x reference)
#include <cuda_runtime.h>
#include <stdint.h>

#define ROWLEN   8192
#define NTHREADS 512
#define NPT      16      // elements per thread (ROWLEN / NTHREADS)
#define KSEL     128
#define CANDN    512     // candidate window capacity

// Per-row top-K of relu(x): keep the K largest positive values, zero the rest.
// Keys: positive float bits (monotone as uint32), non-positive -> 0.
__global__ __launch_bounds__(NTHREADS, 3)
void topk_relu_kernel(const float* __restrict__ x, float* __restrict__ out) {
    __shared__ uint32_t s_cand[CANDN];
    __shared__ uint32_t s_w[32];     // per-warp partials (16 counts + 16 maxes)
    __shared__ uint32_t s_b[4];      // broadcast: [0]=count [1]=max [2]=Tkey [3]=quota
    __shared__ int s_quota;

    const int tid  = threadIdx.x;
    const int wid  = tid >> 5;
    const int lane = tid & 31;
    const size_t base = (size_t)blockIdx.x * ROWLEN;

    // ---- load row, relu -> monotone uint keys (registers, single HBM read) ----
    uint32_t k[NPT];
    {
        const float4* __restrict__ xv = reinterpret_cast<const float4*>(x + base);
#pragma unroll
        for (int i = 0; i < 4; i++) {
            float4 f = xv[tid + i * NTHREADS];
            k[4*i+0] = (f.x > 0.0f) ? __float_as_uint(f.x) : 0u;
            k[4*i+1] = (f.y > 0.0f) ? __float_as_uint(f.y) : 0u;
            k[4*i+2] = (f.z > 0.0f) ? __float_as_uint(f.z) : 0u;
            k[4*i+3] = (f.w > 0.0f) ? __float_as_uint(f.w) : 0u;
        }
    }

    // ---- phase 1: find probe t with KSEL <= count(key >= t) <= CANDN ----
    // Invariant: count(>= lo) >= KSEL, count(>= hi) < KSEL.
    uint32_t lo = 0u, hi = 0x7F800001u;   // count(>=0)=ROWLEN, count(>=inf+1)=0
    uint32_t t  = 0x3FF00000u;            // 1.875f: hits window in 1 pass for N(0,1)
    uint32_t c_hi = 0u;                   // count at current hi
    uint32_t Tkey, kk;
    bool adjacent = false;
    uint32_t cnt = 0;

    for (;;) {
        uint32_t local = 0;
#pragma unroll
        for (int j = 0; j < NPT; j++) local += (k[j] >= t) ? 1u : 0u;
        local = __reduce_add_sync(0xFFFFFFFFu, local);
        if (lane == 0) s_w[wid] = local;
        __syncthreads();
        if (tid < 16) {
            uint32_t v = s_w[tid];
            v += __shfl_xor_sync(0xFFFFu, v, 8);
            v += __shfl_xor_sync(0xFFFFu, v, 4);
            v += __shfl_xor_sync(0xFFFFu, v, 2);
            v += __shfl_xor_sync(0xFFFFu, v, 1);
            if (tid == 0) s_b[0] = v;
        }
        __syncthreads();
        cnt = s_b[0];
        if (cnt >= KSEL && cnt <= CANDN) break;
        if (cnt >= KSEL) { lo = t; } else { hi = t; c_hi = cnt; }
        if (hi - lo <= 1u) { adjacent = true; break; }  // >CANDN-K dups at lo
        t = lo + ((hi - lo) >> 1);
    }

    if (!adjacent) {
        // ---- compact candidates (>= t) to smem via ballot scans; no atomics ----
        if (tid < CANDN) s_cand[tid] = 0u;   // zero-pad
        uint32_t wcnt = 0, mymax = 0;
#pragma unroll
        for (int j = 0; j < NPT; j++) {
            unsigned b = __ballot_sync(0xFFFFFFFFu, k[j] >= t);
            wcnt += __popc(b);
            mymax = (k[j] > mymax) ? k[j] : mymax;
        }
        mymax = __reduce_max_sync(0xFFFFFFFFu, mymax);
        if (lane == 0) { s_w[wid] = wcnt; s_w[16 + wid] = mymax; }
        __syncthreads();
        if (tid < 16) {
            uint32_t v = s_w[tid];
            uint32_t incl = v;
#pragma unroll
            for (int o = 1; o < 16; o <<= 1) {
                uint32_t u = __shfl_up_sync(0xFFFFu, incl, o);
                if (tid >= o) incl += u;
            }
            s_w[tid] = incl - v;             // exclusive warp base
            uint32_t m = s_w[16 + tid];
            m = max(m, __shfl_xor_sync(0xFFFFu, m, 8));
            m = max(m, __shfl_xor_sync(0xFFFFu, m, 4));
            m = max(m, __shfl_xor_sync(0xFFFFu, m, 2));
            m = max(m, __shfl_xor_sync(0xFFFFu, m, 1));
            if (tid == 0) s_b[1] = m;        // block max key
        }
        __syncthreads();
        {
            int run = (int)s_w[wid];
#pragma unroll
            for (int j = 0; j < NPT; j++) {
                bool p = (k[j] >= t);
                unsigned b = __ballot_sync(0xFFFFFFFFu, p);
                if (p) s_cand[run + __popc(b & ((1u << lane) - 1u))] = k[j];
                run += __popc(b);
            }
        }
        __syncthreads();

        // ---- phase 2: warp 0 binary-searches exact K-th largest among candidates ----
        if (wid == 0) {
            uint32_t maxk = s_b[1];
            uint32_t lo2 = t, hi2 = hi, chi2 = c_hi;
            if (maxk + 1u < hi2) { hi2 = maxk + 1u; chi2 = 0u; }
            while (hi2 - lo2 > 1u) {
                uint32_t m = lo2 + ((hi2 - lo2) >> 1);
                uint32_t c = 0;
#pragma unroll
                for (int j = 0; j < NPT; j++)
                    c += (s_cand[lane + j * 32] >= m) ? 1u : 0u;
                c = __reduce_add_sync(0xFFFFFFFFu, c);
                if (c >= KSEL) lo2 = m; else { hi2 = m; chi2 = c; }
            }
            if (lane == 0) { s_b[2] = lo2; s_b[3] = KSEL - chi2; }
        }
        __syncthreads();
        Tkey = s_b[2];
        kk   = s_b[3];
    } else {
        // Degenerate: lo/hi adjacent before window (mass duplicates or <K positives).
        Tkey = lo;
        kk   = KSEL - c_hi;   // exact number of ==Tkey elements to keep
    }

    if (tid == 0) s_quota = (int)kk;
    __syncthreads();

    // ---- output pass straight from registers (single HBM write) ----
    float4* __restrict__ ov = reinterpret_cast<float4*>(out + base);
    const uint32_t T = Tkey;
#pragma unroll
    for (int i = 0; i < 4; i++) {
        float4 o;
        uint32_t a;
        a = k[4*i+0];
        o.x = (a > T) ? __uint_as_float(a)
             : ((a == T && T != 0u && atomicSub(&s_quota, 1) > 0) ? __uint_as_float(a) : 0.0f);
        a = k[4*i+1];
        o.y = (a > T) ? __uint_as_float(a)
             : ((a == T && T != 0u && atomicSub(&s_quota, 1) > 0) ? __uint_as_float(a) : 0.0f);
        a = k[4*i+2];
        o.z = (a > T) ? __uint_as_float(a)
             : ((a == T && T != 0u && atomicSub(&s_quota, 1) > 0) ? __uint_as_float(a) : 0.0f);
        a = k[4*i+3];
        o.w = (a > T) ? __uint_as_float(a)
             : ((a == T && T != 0u && atomicSub(&s_quota, 1) > 0) ? __uint_as_float(a) : 0.0f);
        ov[tid + i * NTHREADS] = o;
    }
}

extern "C" void kernel_launch(void* const* d_in, const int* in_sizes, int n_in,
                              void* d_out, int out_size) {
    const float* x = (const float*)d_in[0];
    float* out = (float*)d_out;
    int rows = in_sizes[0] / ROWLEN;
    topk_relu_kernel<<<rows, NTHREADS>>>(x, out);
}

// round 2
// speedup vs baseline: 1.5471x; 1.5471x over previous
#include <cuda_runtime.h>
#include <stdint.h>

#define ROWLEN   8192
#define NT       512
#define NPT      16       // ROWLEN / NT
#define KSEL     128
#define CANDN    512      // candidate window capacity
#define NBIN     512
#define SHIFT    15       // bin = (bits - t0_bits) >> SHIFT

// Per-row top-K of relu(x). All thresholds > 0 in the main path, so raw float
// compares implement relu implicitly (negatives always fail).
__global__ __launch_bounds__(NT, 3)
void topk_relu_kernel(const float* __restrict__ x, float* __restrict__ out) {
    __shared__ float    s_cand[CANDN];   // compacted candidates (zero-padded)
    __shared__ uint32_t s_hist[NBIN];    // histogram, then reused for suffix sums
    __shared__ float    s_bin[32];       // members of the threshold bin (fast path)
    __shared__ uint32_t s_w[16];         // per-warp partials
    __shared__ uint32_t s_wb[16];        // warp exclusive bases
    __shared__ uint32_t s_meta[6];       // [0]=cnt [1]=b* [2]=above [3]=Tbits [4]=quota [5]=nb
    __shared__ int      s_quota;

    const int tid  = threadIdx.x;
    const int wid  = tid >> 5;
    const int lane = tid & 31;
    const size_t base = (size_t)blockIdx.x * ROWLEN;

    // zero scratch (covered by the first phase-1 barrier)
    s_cand[tid] = 0.0f;
    s_hist[tid] = 0u;
    if (tid == 0) s_meta[5] = 0u;

    // ---- load raw row into registers (single HBM read, no conversion) ----
    float v[NPT];
    {
        const float4* __restrict__ xv = reinterpret_cast<const float4*>(x + base);
#pragma unroll
        for (int i = 0; i < 4; i++) {
            float4 f = xv[tid + i * NT];
            v[4*i+0] = f.x; v[4*i+1] = f.y; v[4*i+2] = f.z; v[4*i+3] = f.w;
        }
    }

    // ---- phase 1: find probe t with KSEL <= count(v >= t) <= CANDN ----
    // Invariant: count(>= lo) >= KSEL  >  count(>= hi)   (uint key space, t > 0)
    uint32_t lo = 0u, hi = 0x7F800001u;
    uint32_t tb = 0x3FF00000u;           // 1.875f: in-window 1st try for N(0,1) rows
    uint32_t c_hi = 0u;
    uint32_t myc = 0, cnt = 0;
    bool adjacent = false;

    for (;;) {
        const float tf = __uint_as_float(tb);
        myc = 0;
#pragma unroll
        for (int j = 0; j < NPT; j++) myc += (v[j] >= tf) ? 1u : 0u;
        uint32_t wsum = __reduce_add_sync(0xFFFFFFFFu, myc);
        if (lane == 0) s_w[wid] = wsum;
        __syncthreads();
        if (tid < 16) {
            uint32_t c = s_w[tid];
            uint32_t incl = c;
#pragma unroll
            for (int o = 1; o < 16; o <<= 1) {
                uint32_t u = __shfl_up_sync(0xFFFFu, incl, o);
                if (tid >= o) incl += u;
            }
            s_wb[tid] = incl - c;                       // exclusive warp base
            if (tid == 15) s_meta[0] = incl;            // block total
        }
        __syncthreads();
        cnt = s_meta[0];
        if (cnt >= KSEL && cnt <= CANDN) break;
        if (cnt >= KSEL) { lo = tb; } else { hi = tb; c_hi = cnt; }
        if (hi - lo <= 1u) { adjacent = true; break; }
        tb = lo + ((hi - lo) >> 1);
    }

    uint32_t Tb, quota;

    if (!adjacent) {
        const float tf = __uint_as_float(tb);

        // ---- compact candidates + build histogram in one pass ----
        uint32_t incl = myc;
#pragma unroll
        for (int o = 1; o < 32; o <<= 1) {
            uint32_t u = __shfl_up_sync(0xFFFFFFFFu, incl, o);
            if (lane >= o) incl += u;
        }
        uint32_t off = s_wb[wid] + incl - myc;
#pragma unroll
        for (int j = 0; j < NPT; j++) {
            if (v[j] >= tf) {
                s_cand[off++] = v[j];
                uint32_t b = (__float_as_uint(v[j]) - tb) >> SHIFT;
                if (b > NBIN - 1u) b = NBIN - 1u;
                atomicAdd(&s_hist[b], 1u);
            }
        }
        __syncthreads();

        // ---- suffix-scan histogram: suf[b] = #candidates in bins >= b ----
        uint32_t h = s_hist[NBIN - 1 - tid];
        uint32_t inc2 = h;
#pragma unroll
        for (int o = 1; o < 32; o <<= 1) {
            uint32_t u = __shfl_up_sync(0xFFFFFFFFu, inc2, o);
            if (lane >= o) inc2 += u;
        }
        if (lane == 31) s_w[wid] = inc2;
        __syncthreads();
        if (tid < 16) {
            uint32_t c = s_w[tid];
            uint32_t i2 = c;
#pragma unroll
            for (int o = 1; o < 16; o <<= 1) {
                uint32_t u = __shfl_up_sync(0xFFFFu, i2, o);
                if (tid >= o) i2 += u;
            }
            s_wb[tid] = i2 - c;
        }
        __syncthreads();
        s_hist[NBIN - 1 - tid] = inc2 + s_wb[wid];      // inclusive suffix sum
        __syncthreads();

        // ---- locate threshold bin b*: suf[b*] >= K > suf[b*+1] ----
        {
            uint32_t sb  = s_hist[tid];
            uint32_t sb1 = (tid == NBIN - 1) ? 0u : s_hist[tid + 1];
            if (sb >= KSEL && sb1 < KSEL) { s_meta[1] = (uint32_t)tid; s_meta[2] = sb1; }
        }
        __syncthreads();
        const uint32_t bstar = s_meta[1];
        const uint32_t above = s_meta[2];

        // ---- extract bin-b* members ----
        if (tid < (int)cnt) {
            float c = s_cand[tid];
            uint32_t b = (__float_as_uint(c) - tb) >> SHIFT;
            if (b > NBIN - 1u) b = NBIN - 1u;
            if (b == bstar) {
                uint32_t p = atomicAdd(&s_meta[5], 1u);
                if (p < 32u) s_bin[p] = c;
            }
        }
        __syncthreads();
        const uint32_t nb = s_meta[5];
        const uint32_t r  = KSEL - above;   // need r-th largest within bin (1 <= r <= nb)

        if (wid == 0) {
            if (nb <= 32u) {
                // warp-shuffle exact rank among <=32 members
                float y = (lane < (int)nb) ? s_bin[lane] : -1.0f;
                uint32_t wgt = 0, wge = 0;
#pragma unroll
                for (int l = 0; l < 32; l++) {
                    float o = __shfl_sync(0xFFFFFFFFu, y, l);
                    if (l < (int)nb) { wgt += (o > y) ? 1u : 0u; wge += (o >= y) ? 1u : 0u; }
                }
                bool pred = (lane < (int)nb) && (wgt < r) && (wge >= r);
                unsigned bal = __ballot_sync(0xFFFFFFFFu, pred);
                if (bal && lane == (int)(__ffs(bal) - 1)) {
                    s_meta[3] = __float_as_uint(y);
                    s_meta[4] = KSEL - (above + wgt);
                }
            } else {
                // rare fallback: binary search within the bin's key range over all candidates
                uint32_t lo2 = tb + (bstar << SHIFT);
                uint32_t hi2 = (bstar == NBIN - 1u) ? 0x7F800001u : tb + ((bstar + 1u) << SHIFT);
                uint32_t chi2 = above;
                while (hi2 - lo2 > 1u) {
                    uint32_t m = lo2 + ((hi2 - lo2) >> 1);
                    float mf = __uint_as_float(m);
                    uint32_t c = 0;
#pragma unroll
                    for (int j = 0; j < CANDN / 32; j++)
                        c += (s_cand[lane + j * 32] >= mf) ? 1u : 0u;
                    c = __reduce_add_sync(0xFFFFFFFFu, c);
                    if (c >= KSEL) lo2 = m; else { hi2 = m; chi2 = c; }
                }
                if (lane == 0) { s_meta[3] = lo2; s_meta[4] = KSEL - chi2; }
            }
        }
        __syncthreads();
        Tb = s_meta[3]; quota = s_meta[4];
    } else {
        // degenerate: mass duplicates / <K positives. T = lo, exact tie quota.
        Tb = lo; quota = KSEL - c_hi;
    }

    if (tid == 0) s_quota = (int)quota;
    __syncthreads();

    // ---- output pass straight from registers (single HBM write) ----
    const float T = __uint_as_float(Tb);
    float4* __restrict__ ov = reinterpret_cast<float4*>(out + base);
#pragma unroll
    for (int i = 0; i < 4; i++) {
        float4 o; float a;
        a = v[4*i+0];
        o.x = (a > T) ? a : ((a == T && atomicSub(&s_quota, 1) > 0) ? fmaxf(a, 0.0f) : 0.0f);
        a = v[4*i+1];
        o.y = (a > T) ? a : ((a == T && atomicSub(&s_quota, 1) > 0) ? fmaxf(a, 0.0f) : 0.0f);
        a = v[4*i+2];
        o.z = (a > T) ? a : ((a == T && atomicSub(&s_quota, 1) > 0) ? fmaxf(a, 0.0f) : 0.0f);
        a = v[4*i+3];
        o.w = (a > T) ? a : ((a == T && atomicSub(&s_quota, 1) > 0) ? fmaxf(a, 0.0f) : 0.0f);
        ov[tid + i * NT] = o;
    }
}

extern "C" void kernel_launch(void* const* d_in, const int* in_sizes, int n_in,
                              void* d_out, int out_size) {
    const float* x = (const float*)d_in[0];
    float* out = (float*)d_out;
    int rows = in_sizes[0] / ROWLEN;
    topk_relu_kernel<<<rows, NT>>>(x, out);
}

// round 3
// speedup vs baseline: 1.6339x; 1.0561x over previous
#include <cuda_runtime.h>
#include <stdint.h>

#define ROWLEN   8192
#define NT       512
#define NPT      16            // ROWLEN / NT
#define KSEL     128
#define NBIN     512           // == NT (one bin per thread)
#define SHIFT    15
#define T0BITS   0x3FF00000u   // 1.875f — in-window first probe for N(0,1) rows

// Per-row top-K of relu(x): keep K largest positive values, zero the rest.
// Thresholds are > 0 in all kept paths, so raw float compares implement relu.
__global__ __launch_bounds__(NT, 3)
void topk_relu_kernel(const float* __restrict__ x, float* __restrict__ out) {
    __shared__ uint32_t s_hist[NBIN];
    __shared__ float    s_bin[32];     // members of threshold bin (fast path)
    __shared__ uint32_t s_w[16];       // per-warp partials
    __shared__ uint32_t s_meta[8];     // 0=b* 1=above 2=nb 3=Tbits 4=quota 5=atomic? 6=found 7=scratch
    __shared__ int      s_quota;

    const int tid  = threadIdx.x;
    const int wid  = tid >> 5;
    const int lane = tid & 31;
    const size_t base = (size_t)blockIdx.x * ROWLEN;

    s_hist[tid] = 0u;
    if (tid < 8) s_meta[tid] = 0u;

    // ---- single HBM read: row -> registers ----
    float v[NPT];
    {
        const float4* __restrict__ xv = reinterpret_cast<const float4*>(x + base);
#pragma unroll
        for (int i = 0; i < 4; i++) {
            float4 f = xv[tid + i * NT];
            v[4*i+0] = f.x; v[4*i+1] = f.y; v[4*i+2] = f.z; v[4*i+3] = f.w;
        }
    }
    __syncthreads();                                   // B1: hist zeros visible

    // ---- histogram of elements >= t0 directly from registers ----
    const float t0 = __uint_as_float(T0BITS);
#pragma unroll
    for (int j = 0; j < NPT; j++) {
        uint32_t b = (__float_as_uint(v[j]) - T0BITS) >> SHIFT;
        if (b > NBIN - 1u) b = NBIN - 1u;              // clamp (garbage for v<t0, unused)
        if (v[j] >= t0) atomicAdd(&s_hist[b], 1u);     // single predicatable op
    }
    __syncthreads();                                   // B2

    // ---- inclusive suffix scan of hist + fused crossing detection ----
    {
        const int rb = NBIN - 1 - tid;                 // bin owned by this thread
        const uint32_t h = s_hist[rb];
        uint32_t incl = h;
#pragma unroll
        for (int o = 1; o < 32; o <<= 1) {
            uint32_t u = __shfl_up_sync(0xFFFFFFFFu, incl, o);
            if (lane >= o) incl += u;
        }
        if (lane == 31) s_w[wid] = incl;
        __syncthreads();                               // B3
        uint32_t wb = 0;
        for (int w = 0; w < wid; w++) wb += s_w[w];    // broadcast smem reads
        const uint32_t suf = incl + wb;                // count of elems in bins >= rb
        if (suf >= KSEL && suf - h < KSEL) {           // unique crossing bin
            s_meta[0] = (uint32_t)rb;
            s_meta[1] = suf - h;                       // count strictly above bin
            s_meta[6] = 1u;
        }
        if (rb == 0) s_meta[7] = suf;                  // total count >= t0 (for fallback)
    }
    __syncthreads();                                   // B4

    uint32_t Tb = 1u;                                  // default: relu-only threshold
    uint32_t quota = 0;
    bool atomic_path = false;

    if (s_meta[6]) {
        // ================= fast path =================
        const uint32_t bstar = s_meta[0];
        const uint32_t above = s_meta[1];
        const bool last = (bstar == NBIN - 1u);
        const float blo = __uint_as_float(T0BITS + (bstar << SHIFT));
        const float bhi = __uint_as_float(T0BITS + ((bstar + 1u) << SHIFT));

        // extract bin-b* members from registers (~1-3 per row)
#pragma unroll
        for (int j = 0; j < NPT; j++) {
            if (v[j] >= blo && (last || v[j] < bhi)) {
                uint32_t p = atomicAdd(&s_meta[2], 1u);
                if (p < 32u) s_bin[p] = v[j];
            }
        }
        __syncthreads();                               // B5
        const uint32_t nb = s_meta[2];
        const uint32_t r  = KSEL - above;              // rank needed within bin

        if (nb <= 32u) {
            if (wid == 0) {                            // warp-shuffle exact rank
                float y = (lane < (int)nb) ? s_bin[lane] : -1.0f;
                uint32_t wgt = 0, wge = 0;
#pragma unroll
                for (int l = 0; l < 32; l++) {
                    float o = __shfl_sync(0xFFFFFFFFu, y, l);
                    if (l < (int)nb) { wgt += (o > y) ? 1u : 0u; wge += (o >= y) ? 1u : 0u; }
                }
                bool pred = (lane < (int)nb) && (wgt < r) && (wge >= r);
                unsigned bal = __ballot_sync(0xFFFFFFFFu, pred);
                if (bal && lane == (int)(__ffs(bal) - 1)) {
                    s_meta[3] = __float_as_uint(y);
                    uint32_t q = r - wgt;              // #ties to keep
                    s_meta[4] = q;
                    s_meta[5] = (q == (wge - wgt)) ? 0u : 1u;  // keep all ties -> no atomics
                }
            }
        } else {
            // rare: >32 equal-bin members -> bit-space binary search over registers
            uint32_t lo2 = T0BITS + (bstar << SHIFT);
            uint32_t hi2 = last ? 0x7F800001u : (T0BITS + ((bstar + 1u) << SHIFT));
            uint32_t chi = above;
            while (hi2 - lo2 > 1u) {
                uint32_t m = lo2 + ((hi2 - lo2) >> 1);
                const float mf = __uint_as_float(m);
                uint32_t c = 0;
#pragma unroll
                for (int j = 0; j < NPT; j++) c += (v[j] >= mf) ? 1u : 0u;
                c = __reduce_add_sync(0xFFFFFFFFu, c);
                if (lane == 0) s_w[wid] = c;
                __syncthreads();
                if (tid == 0) {
                    uint32_t s = 0;
                    for (int w = 0; w < 16; w++) s += s_w[w];
                    s_meta[7] = s;
                }
                __syncthreads();
                uint32_t tot = s_meta[7];
                if (tot >= KSEL) lo2 = m; else { hi2 = m; chi = tot; }
            }
            if (tid == 0) { s_meta[3] = lo2; s_meta[4] = KSEL - chi; s_meta[5] = 1u; }
        }
        __syncthreads();                               // B6
        Tb = s_meta[3]; quota = s_meta[4]; atomic_path = (s_meta[5] != 0u);
    } else {
        // ================= fallback: count(>= t0) < K =================
        uint32_t c_hi = s_meta[7];
        // count positives
        uint32_t cp = 0;
#pragma unroll
        for (int j = 0; j < NPT; j++) cp += (v[j] > 0.0f) ? 1u : 0u;
        cp = __reduce_add_sync(0xFFFFFFFFu, cp);
        if (lane == 0) s_w[wid] = cp;
        __syncthreads();
        if (tid == 0) {
            uint32_t s = 0;
            for (int w = 0; w < 16; w++) s += s_w[w];
            s_meta[7] = s;
        }
        __syncthreads();
        const uint32_t cpos = s_meta[7];

        if (cpos <= KSEL) {
            Tb = 1u; atomic_path = false;              // output = relu(x)
        } else {
            // binary search in bit space (0, t0)
            uint32_t lo2 = 1u, hi2 = T0BITS, chi = c_hi;
            while (hi2 - lo2 > 1u) {
                uint32_t m = lo2 + ((hi2 - lo2) >> 1);
                const float mf = __uint_as_float(m);
                uint32_t c = 0;
#pragma unroll
                for (int j = 0; j < NPT; j++) c += (v[j] >= mf) ? 1u : 0u;
                c = __reduce_add_sync(0xFFFFFFFFu, c);
                if (lane == 0) s_w[wid] = c;
                __syncthreads();
                if (tid == 0) {
                    uint32_t s = 0;
                    for (int w = 0; w < 16; w++) s += s_w[w];
                    s_meta[7] = s;
                }
                __syncthreads();
                uint32_t tot = s_meta[7];
                if (tot >= KSEL) lo2 = m; else { hi2 = m; chi = tot; }
            }
            Tb = lo2; quota = KSEL - chi; atomic_path = true;
        }
    }

    // ---- output pass straight from registers (single HBM write) ----
    float4* __restrict__ ov = reinterpret_cast<float4*>(out + base);
    const float T = __uint_as_float(Tb);

    if (!atomic_path) {
        // common case: keep everything >= T (all ties kept); T > 0 implies relu
#pragma unroll
        for (int i = 0; i < 4; i++) {
            float4 o;
            o.x = (v[4*i+0] >= T) ? v[4*i+0] : 0.0f;
            o.y = (v[4*i+1] >= T) ? v[4*i+1] : 0.0f;
            o.z = (v[4*i+2] >= T) ? v[4*i+2] : 0.0f;
            o.w = (v[4*i+3] >= T) ? v[4*i+3] : 0.0f;
            ov[tid + i * NT] = o;
        }
    } else {
        // rare: partial ties, claim from exact quota
        if (tid == 0) s_quota = (int)quota;
        __syncthreads();
#pragma unroll
        for (int i = 0; i < 4; i++) {
            float4 o; float a;
            a = v[4*i+0];
            o.x = (a > T) ? a : ((a == T && atomicSub(&s_quota, 1) > 0) ? fmaxf(a, 0.0f) : 0.0f);
            a = v[4*i+1];
            o.y = (a > T) ? a : ((a == T && atomicSub(&s_quota, 1) > 0) ? fmaxf(a, 0.0f) : 0.0f);
            a = v[4*i+2];
            o.z = (a > T) ? a : ((a == T && atomicSub(&s_quota, 1) > 0) ? fmaxf(a, 0.0f) : 0.0f);
            a = v[4*i+3];
            o.w = (a > T) ? a : ((a == T && atomicSub(&s_quota, 1) > 0) ? fmaxf(a, 0.0f) : 0.0f);
            ov[tid + i * NT] = o;
        }
    }
}

extern "C" void kernel_launch(void* const* d_in, const int* in_sizes, int n_in,
                              void* d_out, int out_size) {
    const float* x = (const float*)d_in[0];
    float* out = (float*)d_out;
    int rows = in_sizes[0] / ROWLEN;
    topk_relu_kernel<<<rows, NT>>>(x, out);
}